// round 7
// baseline (speedup 1.0000x reference)
#include <cuda_runtime.h>
#include <cuda_fp16.h>
#include <cstdint>

// ---------------- problem constants ----------------
#define BATCH   8192
#define KDIM    4096   // input(2048) + hidden(2048)
#define NDIM    2048   // per-gate output
#define TILE_M  128    // CTA rows
#define TILE_N  32     // CTA cols PER GATE (x4 gates)
#define TILE_K  64     // k-tile (128 bytes fp16 per row)
#define NKT     (KDIM / TILE_K)          // 64
#define M_TILES (BATCH / TILE_M)         // 64
#define N_TILES (NDIM / TILE_N)          // 64
#define GRID    (M_TILES * N_TILES)      // 4096
#define NTHREADS 256                     // 8 warps: 4 along M x 2 along N

// smem per stage: A tile 128x128B = 16KB, W tile (4 gates x 32 rows)x128B = 16KB
#define A_STAGE_BYTES 16384
#define W_STAGE_BYTES 16384
#define STAGE_BYTES   (A_STAGE_BYTES + W_STAGE_BYTES)   // 32768
#define NSTAGES 3
#define SMEM_TOTAL (NSTAGES * STAGE_BYTES)              // 98304

// ---------------- fp16 scratch (device globals: sanctioned scratch path) ---
__device__ __align__(256) __half g_A[(size_t)BATCH * KDIM];     // 67 MB
__device__ __align__(256) __half g_W[(size_t)4 * NDIM * KDIM];  // 67 MB

// ---------------- PTX helpers ----------------
static __device__ __forceinline__ uint32_t smem_u32(const void* p) {
    uint32_t a;
    asm("{ .reg .u64 t; cvta.to.shared.u64 t, %1; cvt.u32.u64 %0, t; }"
        : "=r"(a) : "l"(p));
    return a;
}

static __device__ __forceinline__ void cp_async16(uint32_t saddr, const void* gptr) {
    asm volatile("cp.async.cg.shared.global [%0], [%1], 16;" :: "r"(saddr), "l"(gptr));
}
#define CP_COMMIT() asm volatile("cp.async.commit_group;" ::: "memory")
#define CP_WAIT(n)  asm volatile("cp.async.wait_group %0;" :: "n"(n) : "memory")

#define LDSM_X4(R, addr)                                                     \
    asm volatile("ldmatrix.sync.aligned.m8n8.x4.shared.b16 {%0,%1,%2,%3}, [%4];" \
                 : "=r"((R)[0]), "=r"((R)[1]), "=r"((R)[2]), "=r"((R)[3])    \
                 : "r"(addr))

#define MMA16816(D, A, B0, B1)                                               \
    asm volatile("mma.sync.aligned.m16n8k16.row.col.f32.f16.f16.f32 "        \
                 "{%0,%1,%2,%3}, {%4,%5,%6,%7}, {%8,%9}, {%0,%1,%2,%3};"     \
                 : "+f"((D)[0]), "+f"((D)[1]), "+f"((D)[2]), "+f"((D)[3])    \
                 : "r"((A)[0]), "r"((A)[1]), "r"((A)[2]), "r"((A)[3]),       \
                   "r"(B0), "r"(B1))

// ---------------- activations ----------------
static __device__ __forceinline__ float sigm_f(float x) {
    return __fdividef(1.0f, 1.0f + __expf(-x));
}
static __device__ __forceinline__ float tanh_f(float x) {
    return __fdividef(2.0f, 1.0f + __expf(-2.0f * x)) - 1.0f;
}

// ---------------- pass 1: fp32 -> fp16 conversion (float4 / uint2) --------
// g_A[m][k] = k<2048 ? i[m][k] : h[m][k-2048]
// g_W[g*2048 + n][k] = Wg[n][k]  (gate-major stack == straight per-gate copy)
__global__ void __launch_bounds__(256) convert_kernel(
    const float* __restrict__ i_, const float* __restrict__ h_,
    const float* __restrict__ W1, const float* __restrict__ W2,
    const float* __restrict__ W3, const float* __restrict__ W4) {
    const uint32_t NA4 = (uint32_t)((size_t)BATCH * KDIM / 4);   // 8,388,608
    const uint32_t NW4 = (uint32_t)((size_t)NDIM * KDIM / 4);    // 2,097,152 per gate
    const uint32_t TOT = NA4 + 4 * NW4;
    uint2* Ao = reinterpret_cast<uint2*>(g_A);
    uint2* Wo = reinterpret_cast<uint2*>(g_W);
    uint32_t stride = gridDim.x * blockDim.x;
    for (uint32_t q = blockIdx.x * blockDim.x + threadIdx.x; q < TOT; q += stride) {
        float4 v;
        uint2* dst;
        if (q < NA4) {
            uint32_t m = q >> 10, r = q & 1023;     // 1024 float4 per A row
            if (r < 512) v = reinterpret_cast<const float4*>(i_ + (size_t)m * 2048)[r];
            else         v = reinterpret_cast<const float4*>(h_ + (size_t)m * 2048)[r - 512];
            dst = Ao + q;
        } else {
            uint32_t e = q - NA4;
            uint32_t g = e >> 21, r = e & 0x1FFFFF;  // 2^21 float4 per gate
            const float* W = (g == 0) ? W1 : (g == 1) ? W2 : (g == 2) ? W3 : W4;
            v = reinterpret_cast<const float4*>(W)[r];
            dst = Wo + e;
        }
        __half2 h0 = __floats2half2_rn(v.x, v.y);
        __half2 h1 = __floats2half2_rn(v.z, v.w);
        *dst = make_uint2(*reinterpret_cast<uint32_t*>(&h0),
                          *reinterpret_cast<uint32_t*>(&h1));
    }
}

// ---------------- pass 2: fused 4-gate GEMM + LSTM epilogue ----------------
// 2 CTAs / SM: per-CTA barriers stagger so one CTA's HMMA covers the other's sync.
__global__ void __launch_bounds__(NTHREADS, 2) lstm_gemm_kernel(
    const float* __restrict__ c_,
    const float* __restrict__ b1, const float* __restrict__ b2,
    const float* __restrict__ b3, const float* __restrict__ b4,
    float* __restrict__ hout, float* __restrict__ cout) {
    extern __shared__ char smem[];
    uint32_t sb = smem_u32(smem);
    int tid = threadIdx.x;
    int wid = tid >> 5, lane = tid & 31;
    int wm = wid & 3, wn = wid >> 2;              // 4 warps M x 2 warps N

    // rasterization: 8 groups of 8 m-tiles, m fastest inside group
    int bid = blockIdx.x;
    int group = bid >> 9, local = bid & 511;      // 512 = 8 mt * 64 nt
    int mt = (group << 3) + (local & 7);
    int nt = local >> 3;
    int m0 = mt * TILE_M, n0 = nt * TILE_N;

    // ---- loader state: 2 pointers + 2 smem offsets (strength-reduced) ----
    // chunk i covers rows (tid>>3)+i*32; s = tid&7 fixed; W gate index == i.
    int tr = tid >> 3, ts = tid & 7;
    uint32_t adst0 = (uint32_t)tr * 128 + (uint32_t)((ts ^ (tr & 7)) << 4);
    uint32_t wdst0 = A_STAGE_BYTES + adst0;
    const __half* apt = g_A + (size_t)(m0 + tr) * KDIM + ts * 8;
    const __half* wpt = g_W + (size_t)(n0 + tr) * KDIM + ts * 8;

#define LOAD_STAGE(stagebase) do {                                            \
    _Pragma("unroll")                                                         \
    for (int i_ = 0; i_ < 4; i_++)                                            \
        cp_async16((stagebase) + adst0 + (uint32_t)i_ * 4096,                 \
                   apt + (size_t)i_ * 32 * KDIM);                             \
    _Pragma("unroll")                                                         \
    for (int i_ = 0; i_ < 4; i_++)                                            \
        cp_async16((stagebase) + wdst0 + (uint32_t)i_ * 4096,                 \
                   wpt + (size_t)i_ * NDIM * KDIM);                           \
    CP_COMMIT();                                                              \
    apt += TILE_K; wpt += TILE_K;                                             \
} while (0)

    // ---- per-thread smem read offsets ----
    int l7 = lane & 7;
    int hi16 = lane >> 4;                         // A k-chunk select
    int kh = (lane >> 3) & 1;                     // B k-half select
    uint32_t aks[4], bks[4];
#pragma unroll
    for (int ks = 0; ks < 4; ks++) {
        aks[ks] = (uint32_t)(((2 * ks + hi16) ^ l7) << 4);
        bks[ks] = (uint32_t)(((2 * ks + kh) ^ l7) << 4);
    }
    uint32_t arow[2];
#pragma unroll
    for (int mi = 0; mi < 2; mi++)
        arow[mi] = (uint32_t)(wm * 32 + mi * 16 + (lane & 15)) * 128;
    uint32_t brow[4];
#pragma unroll
    for (int g = 0; g < 4; g++)
        brow[g] = (uint32_t)(g * 32 + wn * 16 + (lane & 7) + ((lane >> 4) << 3)) * 128
                  + A_STAGE_BYTES;

    float acc[4][2][2][4];                        // [gate][mi][ni][frag]
#pragma unroll
    for (int g = 0; g < 4; g++)
#pragma unroll
        for (int mi = 0; mi < 2; mi++)
#pragma unroll
            for (int ni = 0; ni < 2; ni++)
#pragma unroll
                for (int e = 0; e < 4; e++) acc[g][mi][ni][e] = 0.0f;

    LOAD_STAGE(sb);                               // kt = 0
    LOAD_STAGE(sb + STAGE_BYTES);                 // kt = 1

    uint32_t ms = sb;                             // stage holding tile kt
    uint32_t ls = sb + 2 * STAGE_BYTES;           // stage to fill with kt+2

    for (int kt = 0; kt < NKT; kt++) {
        // group for tile kt is second-newest here -> wait_group(1) completes it
        CP_WAIT(1);
        __syncthreads();   // also proves all reads of stage kt-1 are done

        // peel ks=0 fragment loads so HMMA starts before the LDGSTS burst
        uint32_t a[2][4], b[4][4];
#pragma unroll
        for (int mi = 0; mi < 2; mi++) LDSM_X4(a[mi], ms + arow[mi] + aks[0]);
#pragma unroll
        for (int g = 0; g < 4; g++)    LDSM_X4(b[g], ms + brow[g] + bks[0]);

        // stage (kt+2)%3 == (kt-1)%3: safe to overwrite only AFTER the barrier
        if (kt + 2 < NKT) LOAD_STAGE(ls);
        else CP_COMMIT();                         // keep group arithmetic uniform

#pragma unroll
        for (int ks = 0; ks < 4; ks++) {
#pragma unroll
            for (int g = 0; g < 4; g++)
#pragma unroll
                for (int mi = 0; mi < 2; mi++)
#pragma unroll
                    for (int ni = 0; ni < 2; ni++)
                        MMA16816(acc[g][mi][ni], a[mi], b[g][2 * ni], b[g][2 * ni + 1]);
            if (ks < 3) {
#pragma unroll
                for (int mi = 0; mi < 2; mi++) LDSM_X4(a[mi], ms + arow[mi] + aks[ks + 1]);
#pragma unroll
                for (int g = 0; g < 4; g++)    LDSM_X4(b[g], ms + brow[g] + bks[ks + 1]);
            }
        }

        ms += STAGE_BYTES; if (ms == sb + 3 * STAGE_BYTES) ms = sb;
        ls += STAGE_BYTES; if (ls == sb + 3 * STAGE_BYTES) ls = sb;
    }

    // -------- fused LSTM epilogue --------
    int qrow = lane >> 2;
    int qcol = (lane & 3) * 2;
    int colbase = n0 + wn * 16 + qcol;

    float2 bias[4][2];
#pragma unroll
    for (int ni = 0; ni < 2; ni++) {
        bias[0][ni] = *reinterpret_cast<const float2*>(b1 + colbase + ni * 8);
        bias[1][ni] = *reinterpret_cast<const float2*>(b2 + colbase + ni * 8);
        bias[2][ni] = *reinterpret_cast<const float2*>(b3 + colbase + ni * 8);
        bias[3][ni] = *reinterpret_cast<const float2*>(b4 + colbase + ni * 8);
    }

#pragma unroll
    for (int mi = 0; mi < 2; mi++) {
#pragma unroll
        for (int e = 0; e < 2; e++) {             // row half of the m16 tile
            int m = m0 + wm * 32 + mi * 16 + qrow + e * 8;
            const float* crow = c_ + (size_t)m * NDIM;
            float* hrow = hout + (size_t)m * NDIM;
            float* wrow = cout + (size_t)m * NDIM;
#pragma unroll
            for (int ni = 0; ni < 2; ni++) {
                int col = colbase + ni * 8;
                float2 cv = *reinterpret_cast<const float2*>(crow + col);
                float oh[2], oc[2];
#pragma unroll
                for (int p = 0; p < 2; p++) {
                    float bb1 = p ? bias[0][ni].y : bias[0][ni].x;
                    float bb2 = p ? bias[1][ni].y : bias[1][ni].x;
                    float bb3 = p ? bias[2][ni].y : bias[2][ni].x;
                    float bb4 = p ? bias[3][ni].y : bias[3][ni].x;
                    float z1 = acc[0][mi][ni][e * 2 + p] + bb1;
                    float z2 = acc[1][mi][ni][e * 2 + p] + bb2;
                    float z3 = acc[2][mi][ni][e * 2 + p] + bb3;
                    float z4 = acc[3][mi][ni][e * 2 + p] + bb4;
                    float o1 = sigm_f(z1);
                    float o2 = sigm_f(z2);
                    float o3 = tanh_f(z3);
                    float o4 = sigm_f(z4);
                    float cvj = p ? cv.y : cv.x;
                    oc[p] = cvj * o1 + o2 * o3;
                    oh[p] = tanh_f(cvj) * o4;
                }
                *reinterpret_cast<float2*>(hrow + col) = make_float2(oh[0], oh[1]);
                *reinterpret_cast<float2*>(wrow + col) = make_float2(oc[0], oc[1]);
            }
        }
    }
}

// ---------------- launcher ----------------
extern "C" void kernel_launch(void* const* d_in, const int* in_sizes, int n_in,
                              void* d_out, int out_size) {
    const float* i_ = (const float*)d_in[0];
    const float* h_ = (const float*)d_in[1];
    const float* c_ = (const float*)d_in[2];
    const float* W1 = (const float*)d_in[3];
    const float* b1 = (const float*)d_in[4];
    const float* W2 = (const float*)d_in[5];
    const float* b2 = (const float*)d_in[6];
    const float* W3 = (const float*)d_in[7];
    const float* b3 = (const float*)d_in[8];
    const float* W4 = (const float*)d_in[9];
    const float* b4 = (const float*)d_in[10];
    float* out = (float*)d_out;

    cudaFuncSetAttribute(lstm_gemm_kernel,
                         cudaFuncAttributeMaxDynamicSharedMemorySize, SMEM_TOTAL);

    convert_kernel<<<8192, 256>>>(i_, h_, W1, W2, W3, W4);
    lstm_gemm_kernel<<<GRID, NTHREADS, SMEM_TOTAL>>>(
        c_, b1, b2, b3, b4, out, out + (size_t)BATCH * NDIM);
}

// round 10
// speedup vs baseline: 1.0871x; 1.0871x over previous
#include <cuda_runtime.h>
#include <cuda_fp16.h>
#include <cstdint>

// ---------------- problem constants ----------------
#define BATCH   8192
#define KDIM    4096   // input(2048) + hidden(2048)
#define NDIM    2048   // per-gate output
#define TILE_M  128    // CTA rows
#define TILE_N  32     // CTA cols PER GATE (x4 gates)
#define TILE_K  64     // k-tile (128 bytes fp16 per row)
#define NKT     (KDIM / TILE_K)          // 64
#define M_TILES (BATCH / TILE_M)         // 64
#define N_TILES (NDIM / TILE_N)          // 64
#define GRID    (M_TILES * N_TILES)      // 4096
#define NTHREADS 128                     // 4 warps: 2 along M x 2 along N (m64 x n64 warp tile)

// smem per stage: A tile 128x128B = 16KB, W tile (4 gates x 32 rows)x128B = 16KB
#define A_STAGE_BYTES 16384
#define W_STAGE_BYTES 16384
#define STAGE_BYTES   (A_STAGE_BYTES + W_STAGE_BYTES)   // 32768
#define NSTAGES 3
#define SMEM_TOTAL (NSTAGES * STAGE_BYTES)              // 98304

// ---------------- fp16 scratch (device globals: sanctioned scratch path) ---
__device__ __align__(256) __half g_A[(size_t)BATCH * KDIM];     // 67 MB
__device__ __align__(256) __half g_W[(size_t)4 * NDIM * KDIM];  // 67 MB

// ---------------- PTX helpers ----------------
static __device__ __forceinline__ uint32_t smem_u32(const void* p) {
    uint32_t a;
    asm("{ .reg .u64 t; cvta.to.shared.u64 t, %1; cvt.u32.u64 %0, t; }"
        : "=r"(a) : "l"(p));
    return a;
}

static __device__ __forceinline__ void cp_async16(uint32_t saddr, const void* gptr) {
    asm volatile("cp.async.cg.shared.global [%0], [%1], 16;" :: "r"(saddr), "l"(gptr));
}
#define CP_COMMIT() asm volatile("cp.async.commit_group;" ::: "memory")
#define CP_WAIT(n)  asm volatile("cp.async.wait_group %0;" :: "n"(n) : "memory")

#define LDSM_X4(R, addr)                                                     \
    asm volatile("ldmatrix.sync.aligned.m8n8.x4.shared.b16 {%0,%1,%2,%3}, [%4];" \
                 : "=r"((R)[0]), "=r"((R)[1]), "=r"((R)[2]), "=r"((R)[3])    \
                 : "r"(addr))

#define MMA16816(D, A, B0, B1)                                               \
    asm volatile("mma.sync.aligned.m16n8k16.row.col.f32.f16.f16.f32 "        \
                 "{%0,%1,%2,%3}, {%4,%5,%6,%7}, {%8,%9}, {%0,%1,%2,%3};"     \
                 : "+f"((D)[0]), "+f"((D)[1]), "+f"((D)[2]), "+f"((D)[3])    \
                 : "r"((A)[0]), "r"((A)[1]), "r"((A)[2]), "r"((A)[3]),       \
                   "r"(B0), "r"(B1))

// ---------------- activations ----------------
static __device__ __forceinline__ float sigm_f(float x) {
    return __fdividef(1.0f, 1.0f + __expf(-x));
}
static __device__ __forceinline__ float tanh_f(float x) {
    return __fdividef(2.0f, 1.0f + __expf(-2.0f * x)) - 1.0f;
}

// ---------------- pass 1: fp32 -> fp16 conversion (float4 / uint2) --------
// g_A[m][k] = k<2048 ? i[m][k] : h[m][k-2048]
// g_W[g*2048 + n][k] = Wg[n][k]  (gate-major stack == straight per-gate copy)
__global__ void __launch_bounds__(256) convert_kernel(
    const float* __restrict__ i_, const float* __restrict__ h_,
    const float* __restrict__ W1, const float* __restrict__ W2,
    const float* __restrict__ W3, const float* __restrict__ W4) {
    const uint32_t NA4 = (uint32_t)((size_t)BATCH * KDIM / 4);   // 8,388,608
    const uint32_t NW4 = (uint32_t)((size_t)NDIM * KDIM / 4);    // 2,097,152 per gate
    const uint32_t TOT = NA4 + 4 * NW4;
    uint2* Ao = reinterpret_cast<uint2*>(g_A);
    uint2* Wo = reinterpret_cast<uint2*>(g_W);
    uint32_t stride = gridDim.x * blockDim.x;
    for (uint32_t q = blockIdx.x * blockDim.x + threadIdx.x; q < TOT; q += stride) {
        float4 v;
        uint2* dst;
        if (q < NA4) {
            uint32_t m = q >> 10, r = q & 1023;     // 1024 float4 per A row
            if (r < 512) v = reinterpret_cast<const float4*>(i_ + (size_t)m * 2048)[r];
            else         v = reinterpret_cast<const float4*>(h_ + (size_t)m * 2048)[r - 512];
            dst = Ao + q;
        } else {
            uint32_t e = q - NA4;
            uint32_t g = e >> 21, r = e & 0x1FFFFF;  // 2^21 float4 per gate
            const float* W = (g == 0) ? W1 : (g == 1) ? W2 : (g == 2) ? W3 : W4;
            v = reinterpret_cast<const float4*>(W)[r];
            dst = Wo + e;
        }
        __half2 h0 = __floats2half2_rn(v.x, v.y);
        __half2 h1 = __floats2half2_rn(v.z, v.w);
        *dst = make_uint2(*reinterpret_cast<uint32_t*>(&h0),
                          *reinterpret_cast<uint32_t*>(&h1));
    }
}

// ---------------- pass 2: fused 4-gate GEMM + LSTM epilogue ----------------
// 2 CTAs / SM (128 thr each): per-CTA barriers stagger; warp tile m64 x n64
// cuts LDSM traffic to 128 B/HMMA (8 LDSM.x4 feed 32 HMMA per k16 step).
__global__ void __launch_bounds__(NTHREADS, 2) lstm_gemm_kernel(
    const float* __restrict__ c_,
    const float* __restrict__ b1, const float* __restrict__ b2,
    const float* __restrict__ b3, const float* __restrict__ b4,
    float* __restrict__ hout, float* __restrict__ cout) {
    extern __shared__ char smem[];
    uint32_t sb = smem_u32(smem);
    int tid = threadIdx.x;
    int wid = tid >> 5, lane = tid & 31;
    int wm = wid & 1, wn = wid >> 1;              // 2 warps M x 2 warps N

    // rasterization: 8 groups of 8 m-tiles, m fastest inside group
    int bid = blockIdx.x;
    int group = bid >> 9, local = bid & 511;      // 512 = 8 mt * 64 nt
    int mt = (group << 3) + (local & 7);
    int nt = local >> 3;
    int m0 = mt * TILE_M, n0 = nt * TILE_N;

    // ---- loader state: 2 pointers + 2 smem offsets (strength-reduced) ----
    // 128 threads, 16 chunks each (8 A + 8 W); rows (tid>>3) + i*16.
    int tr = tid >> 3, ts = tid & 7;              // tr: 0..15, ts: 0..7
    uint32_t adst0 = (uint32_t)tr * 128 + (uint32_t)((ts ^ (tr & 7)) << 4);
    uint32_t wdst0 = A_STAGE_BYTES + adst0;       // (16*i rows keep (r&7) == tr&7)
    const __half* apt = g_A + (size_t)(m0 + tr) * KDIM + ts * 8;
    const __half* wpt = g_W + (size_t)(n0 + tr) * KDIM + ts * 8;

    // W tile row wr = tr + 16*i: gate = i>>1, local n = tr + 16*(i&1)
#define LOAD_STAGE(stagebase) do {                                            \
    _Pragma("unroll")                                                         \
    for (int i_ = 0; i_ < 8; i_++)                                            \
        cp_async16((stagebase) + adst0 + (uint32_t)i_ * 2048,                 \
                   apt + (size_t)i_ * 16 * KDIM);                             \
    _Pragma("unroll")                                                         \
    for (int i_ = 0; i_ < 8; i_++)                                            \
        cp_async16((stagebase) + wdst0 + (uint32_t)i_ * 2048,                 \
                   wpt + ((size_t)(i_ >> 1) * NDIM + (size_t)(i_ & 1) * 16) * KDIM); \
    CP_COMMIT();                                                              \
    apt += TILE_K; wpt += TILE_K;                                             \
} while (0)

    // ---- per-thread smem read offsets ----
    int l7 = lane & 7;
    int hi16 = lane >> 4;                         // A k-chunk select
    int kh = (lane >> 3) & 1;                     // B k-half select
    uint32_t aks[4], bks[4];
#pragma unroll
    for (int ks = 0; ks < 4; ks++) {
        aks[ks] = (uint32_t)(((2 * ks + hi16) ^ l7) << 4);
        bks[ks] = (uint32_t)(((2 * ks + kh) ^ l7) << 4);
    }
    uint32_t arow[4];
#pragma unroll
    for (int mi = 0; mi < 4; mi++)
        arow[mi] = (uint32_t)(wm * 64 + mi * 16 + (lane & 15)) * 128;
    uint32_t brow[4];
#pragma unroll
    for (int g = 0; g < 4; g++)
        brow[g] = (uint32_t)(g * 32 + wn * 16 + (lane & 7) + ((lane >> 4) << 3)) * 128
                  + A_STAGE_BYTES;

    float acc[4][4][2][4];                        // [gate][mi][ni][frag] = 128 regs
#pragma unroll
    for (int g = 0; g < 4; g++)
#pragma unroll
        for (int mi = 0; mi < 4; mi++)
#pragma unroll
            for (int ni = 0; ni < 2; ni++)
#pragma unroll
                for (int e = 0; e < 4; e++) acc[g][mi][ni][e] = 0.0f;

    LOAD_STAGE(sb);                               // kt = 0
    LOAD_STAGE(sb + STAGE_BYTES);                 // kt = 1

    uint32_t ms = sb;                             // stage holding tile kt
    uint32_t ls = sb + 2 * STAGE_BYTES;           // stage to fill with kt+2

    for (int kt = 0; kt < NKT; kt++) {
        // group for tile kt is second-newest here -> wait_group(1) completes it
        CP_WAIT(1);
        __syncthreads();   // also proves all reads of stage kt-1 are done

        // double-buffered fragments: load ks=0 set, then issue loads for ks+1
        // before each 32-MMA chain so LDSM latency hides under tensor work.
        uint32_t a[2][4][4], b[2][4][4];
#pragma unroll
        for (int mi = 0; mi < 4; mi++) LDSM_X4(a[0][mi], ms + arow[mi] + aks[0]);
#pragma unroll
        for (int g = 0; g < 4; g++)    LDSM_X4(b[0][g], ms + brow[g] + bks[0]);

        // stage (kt+2)%3 == (kt-1)%3: safe to overwrite only AFTER the barrier
        if (kt + 2 < NKT) LOAD_STAGE(ls);
        else CP_COMMIT();                         // keep group arithmetic uniform

#pragma unroll
        for (int ks = 0; ks < 4; ks++) {
            int cur = ks & 1, nxt = cur ^ 1;
            if (ks < 3) {
#pragma unroll
                for (int mi = 0; mi < 4; mi++) LDSM_X4(a[nxt][mi], ms + arow[mi] + aks[ks + 1]);
#pragma unroll
                for (int g = 0; g < 4; g++)    LDSM_X4(b[nxt][g], ms + brow[g] + bks[ks + 1]);
            }
#pragma unroll
            for (int g = 0; g < 4; g++)
#pragma unroll
                for (int mi = 0; mi < 4; mi++)
#pragma unroll
                    for (int ni = 0; ni < 2; ni++)
                        MMA16816(acc[g][mi][ni], a[cur][mi],
                                 b[cur][g][2 * ni], b[cur][g][2 * ni + 1]);
        }

        ms += STAGE_BYTES; if (ms == sb + 3 * STAGE_BYTES) ms = sb;
        ls += STAGE_BYTES; if (ls == sb + 3 * STAGE_BYTES) ls = sb;
    }

    // -------- fused LSTM epilogue --------
    int qrow = lane >> 2;
    int qcol = (lane & 3) * 2;
    int colbase = n0 + wn * 16 + qcol;

    float2 bias[4][2];
#pragma unroll
    for (int ni = 0; ni < 2; ni++) {
        bias[0][ni] = *reinterpret_cast<const float2*>(b1 + colbase + ni * 8);
        bias[1][ni] = *reinterpret_cast<const float2*>(b2 + colbase + ni * 8);
        bias[2][ni] = *reinterpret_cast<const float2*>(b3 + colbase + ni * 8);
        bias[3][ni] = *reinterpret_cast<const float2*>(b4 + colbase + ni * 8);
    }

#pragma unroll
    for (int mi = 0; mi < 4; mi++) {
#pragma unroll
        for (int e = 0; e < 2; e++) {             // row half of the m16 tile
            int m = m0 + wm * 64 + mi * 16 + qrow + e * 8;
            const float* crow = c_ + (size_t)m * NDIM;
            float* hrow = hout + (size_t)m * NDIM;
            float* wrow = cout + (size_t)m * NDIM;
#pragma unroll
            for (int ni = 0; ni < 2; ni++) {
                int col = colbase + ni * 8;
                float2 cv = *reinterpret_cast<const float2*>(crow + col);
                float oh[2], oc[2];
#pragma unroll
                for (int p = 0; p < 2; p++) {
                    float bb1 = p ? bias[0][ni].y : bias[0][ni].x;
                    float bb2 = p ? bias[1][ni].y : bias[1][ni].x;
                    float bb3 = p ? bias[2][ni].y : bias[2][ni].x;
                    float bb4 = p ? bias[3][ni].y : bias[3][ni].x;
                    float z1 = acc[0][mi][ni][e * 2 + p] + bb1;
                    float z2 = acc[1][mi][ni][e * 2 + p] + bb2;
                    float z3 = acc[2][mi][ni][e * 2 + p] + bb3;
                    float z4 = acc[3][mi][ni][e * 2 + p] + bb4;
                    float o1 = sigm_f(z1);
                    float o2 = sigm_f(z2);
                    float o3 = tanh_f(z3);
                    float o4 = sigm_f(z4);
                    float cvj = p ? cv.y : cv.x;
                    oc[p] = cvj * o1 + o2 * o3;
                    oh[p] = tanh_f(cvj) * o4;
                }
                *reinterpret_cast<float2*>(hrow + col) = make_float2(oh[0], oh[1]);
                *reinterpret_cast<float2*>(wrow + col) = make_float2(oc[0], oc[1]);
            }
        }
    }
}

// ---------------- launcher ----------------
extern "C" void kernel_launch(void* const* d_in, const int* in_sizes, int n_in,
                              void* d_out, int out_size) {
    const float* i_ = (const float*)d_in[0];
    const float* h_ = (const float*)d_in[1];
    const float* c_ = (const float*)d_in[2];
    const float* W1 = (const float*)d_in[3];
    const float* b1 = (const float*)d_in[4];
    const float* W2 = (const float*)d_in[5];
    const float* b2 = (const float*)d_in[6];
    const float* W3 = (const float*)d_in[7];
    const float* b3 = (const float*)d_in[8];
    const float* W4 = (const float*)d_in[9];
    const float* b4 = (const float*)d_in[10];
    float* out = (float*)d_out;

    cudaFuncSetAttribute(lstm_gemm_kernel,
                         cudaFuncAttributeMaxDynamicSharedMemorySize, SMEM_TOTAL);

    convert_kernel<<<8192, 256>>>(i_, h_, W1, W2, W3, W4);
    lstm_gemm_kernel<<<GRID, NTHREADS, SMEM_TOTAL>>>(
        c_, b1, b2, b3, b4, out, out + (size_t)BATCH * NDIM);
}

// round 12
// speedup vs baseline: 1.2121x; 1.1150x over previous
#include <cuda_runtime.h>
#include <cuda_fp16.h>
#include <cstdint>

// ---------------- problem constants ----------------
#define BATCH   8192
#define KDIM    4096   // input(2048) + hidden(2048)
#define NDIM    2048   // per-gate output
#define TILE_M  128    // CTA rows
#define TILE_N  32     // CTA cols PER GATE (x4 gates)
#define TILE_K  64     // k-tile (128 bytes fp16 per row)
#define NKT     (KDIM / TILE_K)          // 64
#define M_TILES (BATCH / TILE_M)         // 64
#define N_TILES (NDIM / TILE_N)          // 64
#define GRID    (M_TILES * N_TILES)      // 4096
#define NTHREADS 128                     // 4 warps: 2 along M x 2 along N (m64 x n64 warp tile)

// smem per stage: A tile 128x128B = 16KB, W tile (4 gates x 32 rows)x128B = 16KB
#define A_STAGE_BYTES 16384
#define W_STAGE_BYTES 16384
#define STAGE_BYTES   (A_STAGE_BYTES + W_STAGE_BYTES)   // 32768
#define NSTAGES 3
#define SMEM_TOTAL (NSTAGES * STAGE_BYTES)              // 98304

// ---------------- fp16 scratch (device globals: sanctioned scratch path) ---
__device__ __align__(256) __half g_A[(size_t)BATCH * KDIM];     // 67 MB
__device__ __align__(256) __half g_W[(size_t)4 * NDIM * KDIM];  // 67 MB

// ---------------- PTX helpers ----------------
static __device__ __forceinline__ uint32_t smem_u32(const void* p) {
    uint32_t a;
    asm("{ .reg .u64 t; cvta.to.shared.u64 t, %1; cvt.u32.u64 %0, t; }"
        : "=r"(a) : "l"(p));
    return a;
}

static __device__ __forceinline__ void cp_async16(uint32_t saddr, const void* gptr) {
    asm volatile("cp.async.cg.shared.global [%0], [%1], 16;" :: "r"(saddr), "l"(gptr));
}
#define CP_COMMIT() asm volatile("cp.async.commit_group;" ::: "memory")
#define CP_WAIT(n)  asm volatile("cp.async.wait_group %0;" :: "n"(n) : "memory")

#define LDSM_X4(R, addr)                                                     \
    asm volatile("ldmatrix.sync.aligned.m8n8.x4.shared.b16 {%0,%1,%2,%3}, [%4];" \
                 : "=r"((R)[0]), "=r"((R)[1]), "=r"((R)[2]), "=r"((R)[3])    \
                 : "r"(addr))

#define MMA16816(D, A, B0, B1)                                               \
    asm volatile("mma.sync.aligned.m16n8k16.row.col.f32.f16.f16.f32 "        \
                 "{%0,%1,%2,%3}, {%4,%5,%6,%7}, {%8,%9}, {%0,%1,%2,%3};"     \
                 : "+f"((D)[0]), "+f"((D)[1]), "+f"((D)[2]), "+f"((D)[3])    \
                 : "r"((A)[0]), "r"((A)[1]), "r"((A)[2]), "r"((A)[3]),       \
                   "r"(B0), "r"(B1))

// ---------------- activations ----------------
static __device__ __forceinline__ float sigm_f(float x) {
    return __fdividef(1.0f, 1.0f + __expf(-x));
}
static __device__ __forceinline__ float tanh_f(float x) {
    return __fdividef(2.0f, 1.0f + __expf(-2.0f * x)) - 1.0f;
}

// ---------------- pass 1: fp32 -> fp16 conversion (float4 / uint2) --------
// g_A[m][k] = k<2048 ? i[m][k] : h[m][k-2048]
// g_W[g*2048 + n][k] = Wg[n][k]  (gate-major stack == straight per-gate copy)
__global__ void __launch_bounds__(256) convert_kernel(
    const float* __restrict__ i_, const float* __restrict__ h_,
    const float* __restrict__ W1, const float* __restrict__ W2,
    const float* __restrict__ W3, const float* __restrict__ W4) {
    const uint32_t NA4 = (uint32_t)((size_t)BATCH * KDIM / 4);   // 8,388,608
    const uint32_t NW4 = (uint32_t)((size_t)NDIM * KDIM / 4);    // 2,097,152 per gate
    const uint32_t TOT = NA4 + 4 * NW4;
    uint2* Ao = reinterpret_cast<uint2*>(g_A);
    uint2* Wo = reinterpret_cast<uint2*>(g_W);
    uint32_t stride = gridDim.x * blockDim.x;
    for (uint32_t q = blockIdx.x * blockDim.x + threadIdx.x; q < TOT; q += stride) {
        float4 v;
        uint2* dst;
        if (q < NA4) {
            uint32_t m = q >> 10, r = q & 1023;     // 1024 float4 per A row
            if (r < 512) v = reinterpret_cast<const float4*>(i_ + (size_t)m * 2048)[r];
            else         v = reinterpret_cast<const float4*>(h_ + (size_t)m * 2048)[r - 512];
            dst = Ao + q;
        } else {
            uint32_t e = q - NA4;
            uint32_t g = e >> 21, r = e & 0x1FFFFF;  // 2^21 float4 per gate
            const float* W = (g == 0) ? W1 : (g == 1) ? W2 : (g == 2) ? W3 : W4;
            v = reinterpret_cast<const float4*>(W)[r];
            dst = Wo + e;
        }
        __half2 h0 = __floats2half2_rn(v.x, v.y);
        __half2 h1 = __floats2half2_rn(v.z, v.w);
        *dst = make_uint2(*reinterpret_cast<uint32_t*>(&h0),
                          *reinterpret_cast<uint32_t*>(&h1));
    }
}

// ---------------- pass 2: fused 4-gate GEMM + LSTM epilogue ----------------
// 2 CTAs / SM (128 thr each); warp tile m64 x n64.
// Re-scheduled pipeline: CP_WAIT + barrier + ks0-fragment preload at the END
// of each k-iteration, so every iteration begins issuing HMMA immediately;
// the 16 cp.async issues are spread 4-per-ks-group to smooth LSU pressure.
__global__ void __launch_bounds__(NTHREADS, 2) lstm_gemm_kernel(
    const float* __restrict__ c_,
    const float* __restrict__ b1, const float* __restrict__ b2,
    const float* __restrict__ b3, const float* __restrict__ b4,
    float* __restrict__ hout, float* __restrict__ cout) {
    extern __shared__ char smem[];
    uint32_t sb = smem_u32(smem);
    int tid = threadIdx.x;
    int wid = tid >> 5, lane = tid & 31;
    int wm = wid & 1, wn = wid >> 1;              // 2 warps M x 2 warps N

    // rasterization: 8 groups of 8 m-tiles, m fastest inside group
    int bid = blockIdx.x;
    int group = bid >> 9, local = bid & 511;      // 512 = 8 mt * 64 nt
    int mt = (group << 3) + (local & 7);
    int nt = local >> 3;
    int m0 = mt * TILE_M, n0 = nt * TILE_N;

    // ---- loader state: 2 pointers + 2 smem offsets (strength-reduced) ----
    // 128 threads, 16 chunks each (8 A + 8 W); rows (tid>>3) + i*16.
    int tr = tid >> 3, ts = tid & 7;              // tr: 0..15, ts: 0..7
    uint32_t adst0 = (uint32_t)tr * 128 + (uint32_t)((ts ^ (tr & 7)) << 4);
    uint32_t wdst0 = A_STAGE_BYTES + adst0;       // (16*i rows keep (r&7) == tr&7)
    const __half* apt = g_A + (size_t)(m0 + tr) * KDIM + ts * 8;
    const __half* wpt = g_W + (size_t)(n0 + tr) * KDIM + ts * 8;

    // A chunk i (i=0..7): smem +i*2048, gmem +i*16*KDIM
    // W chunk i (i=0..7): gate = i>>1, local row offset 16*(i&1)
#define LOAD_A_CHUNKS(stagebase, I0)                                          \
    _Pragma("unroll")                                                         \
    for (int i_ = (I0); i_ < (I0) + 4; i_++)                                  \
        cp_async16((stagebase) + adst0 + (uint32_t)i_ * 2048,                 \
                   apt + (size_t)i_ * 16 * KDIM)
#define LOAD_W_CHUNKS(stagebase, I0)                                          \
    _Pragma("unroll")                                                         \
    for (int i_ = (I0); i_ < (I0) + 4; i_++)                                  \
        cp_async16((stagebase) + wdst0 + (uint32_t)i_ * 2048,                 \
                   wpt + ((size_t)(i_ >> 1) * NDIM + (size_t)(i_ & 1) * 16) * KDIM)

    // ---- per-thread smem read offsets ----
    int l7 = lane & 7;
    int hi16 = lane >> 4;                         // A k-chunk select
    int kh = (lane >> 3) & 1;                     // B k-half select
    uint32_t aks[4], bks[4];
#pragma unroll
    for (int ks = 0; ks < 4; ks++) {
        aks[ks] = (uint32_t)(((2 * ks + hi16) ^ l7) << 4);
        bks[ks] = (uint32_t)(((2 * ks + kh) ^ l7) << 4);
    }
    uint32_t arow[4];
#pragma unroll
    for (int mi = 0; mi < 4; mi++)
        arow[mi] = (uint32_t)(wm * 64 + mi * 16 + (lane & 15)) * 128;
    uint32_t brow[4];
#pragma unroll
    for (int g = 0; g < 4; g++)
        brow[g] = (uint32_t)(g * 32 + wn * 16 + (lane & 7) + ((lane >> 4) << 3)) * 128
                  + A_STAGE_BYTES;

    float acc[4][4][2][4];                        // [gate][mi][ni][frag] = 128 regs
#pragma unroll
    for (int g = 0; g < 4; g++)
#pragma unroll
        for (int mi = 0; mi < 4; mi++)
#pragma unroll
            for (int ni = 0; ni < 2; ni++)
#pragma unroll
                for (int e = 0; e < 4; e++) acc[g][mi][ni][e] = 0.0f;

    // ---- prologue: fill stages 0 and 1, preload tile-0 ks0 fragments ----
    LOAD_A_CHUNKS(sb, 0); LOAD_A_CHUNKS(sb, 4);
    LOAD_W_CHUNKS(sb, 0); LOAD_W_CHUNKS(sb, 4);
    CP_COMMIT();
    apt += TILE_K; wpt += TILE_K;
    LOAD_A_CHUNKS(sb + STAGE_BYTES, 0); LOAD_A_CHUNKS(sb + STAGE_BYTES, 4);
    LOAD_W_CHUNKS(sb + STAGE_BYTES, 0); LOAD_W_CHUNKS(sb + STAGE_BYTES, 4);
    CP_COMMIT();
    apt += TILE_K; wpt += TILE_K;

    CP_WAIT(1);                                   // stage 0 complete
    __syncthreads();                              // visible CTA-wide

    uint32_t a[2][4][4], b[2][4][4];
    uint32_t ms = sb;                             // stage holding tile kt
    uint32_t ls = sb + 2 * STAGE_BYTES;           // stage to fill with kt+2
#pragma unroll
    for (int mi = 0; mi < 4; mi++) LDSM_X4(a[0][mi], ms + arow[mi] + aks[0]);
#pragma unroll
    for (int g = 0; g < 4; g++)    LDSM_X4(b[0][g], ms + brow[g] + bks[0]);

    for (int kt = 0; kt < NKT; kt++) {
        bool doload = (kt + 2 < NKT);
#pragma unroll
        for (int ks = 0; ks < 4; ks++) {
            int cur = ks & 1, nxt = cur ^ 1;
            if (ks < 3) {
#pragma unroll
                for (int mi = 0; mi < 4; mi++) LDSM_X4(a[nxt][mi], ms + arow[mi] + aks[ks + 1]);
#pragma unroll
                for (int g = 0; g < 4; g++)    LDSM_X4(b[nxt][g], ms + brow[g] + bks[ks + 1]);
            }
            if (doload) {                         // 4 cp.async per ks group
                if (ks == 0) { LOAD_A_CHUNKS(ls, 0); }
                if (ks == 1) { LOAD_A_CHUNKS(ls, 4); }
                if (ks == 2) { LOAD_W_CHUNKS(ls, 0); }
                if (ks == 3) { LOAD_W_CHUNKS(ls, 4); }
            }
#pragma unroll
            for (int g = 0; g < 4; g++)
#pragma unroll
                for (int mi = 0; mi < 4; mi++)
#pragma unroll
                    for (int ni = 0; ni < 2; ni++)
                        MMA16816(acc[g][mi][ni], a[cur][mi],
                                 b[cur][g][2 * ni], b[cur][g][2 * ni + 1]);
        }
        CP_COMMIT();                              // close group for tile kt+2
        apt += TILE_K; wpt += TILE_K;

        // outstanding groups: {kt+1, kt+2} -> wait(1) completes tile kt+1
        CP_WAIT(1);
        __syncthreads();   // stage kt+1 visible CTA-wide; stage-kt reads proven done

        ms += STAGE_BYTES; if (ms == sb + 3 * STAGE_BYTES) ms = sb;
        ls += STAGE_BYTES; if (ls == sb + 3 * STAGE_BYTES) ls = sb;

        if (kt + 1 < NKT) {                       // preload ks0 frags of tile kt+1
#pragma unroll
            for (int mi = 0; mi < 4; mi++) LDSM_X4(a[0][mi], ms + arow[mi] + aks[0]);
#pragma unroll
            for (int g = 0; g < 4; g++)    LDSM_X4(b[0][g], ms + brow[g] + bks[0]);
        }
    }

    // -------- fused LSTM epilogue --------
    int qrow = lane >> 2;
    int qcol = (lane & 3) * 2;
    int colbase = n0 + wn * 16 + qcol;

    float2 bias[4][2];
#pragma unroll
    for (int ni = 0; ni < 2; ni++) {
        bias[0][ni] = *reinterpret_cast<const float2*>(b1 + colbase + ni * 8);
        bias[1][ni] = *reinterpret_cast<const float2*>(b2 + colbase + ni * 8);
        bias[2][ni] = *reinterpret_cast<const float2*>(b3 + colbase + ni * 8);
        bias[3][ni] = *reinterpret_cast<const float2*>(b4 + colbase + ni * 8);
    }

#pragma unroll
    for (int mi = 0; mi < 4; mi++) {
#pragma unroll
        for (int e = 0; e < 2; e++) {             // row half of the m16 tile
            int m = m0 + wm * 64 + mi * 16 + qrow + e * 8;
            const float* crow = c_ + (size_t)m * NDIM;
            float* hrow = hout + (size_t)m * NDIM;
            float* wrow = cout + (size_t)m * NDIM;
#pragma unroll
            for (int ni = 0; ni < 2; ni++) {
                int col = colbase + ni * 8;
                float2 cv = *reinterpret_cast<const float2*>(crow + col);
                float oh[2], oc[2];
#pragma unroll
                for (int p = 0; p < 2; p++) {
                    float bb1 = p ? bias[0][ni].y : bias[0][ni].x;
                    float bb2 = p ? bias[1][ni].y : bias[1][ni].x;
                    float bb3 = p ? bias[2][ni].y : bias[2][ni].x;
                    float bb4 = p ? bias[3][ni].y : bias[3][ni].x;
                    float z1 = acc[0][mi][ni][e * 2 + p] + bb1;
                    float z2 = acc[1][mi][ni][e * 2 + p] + bb2;
                    float z3 = acc[2][mi][ni][e * 2 + p] + bb3;
                    float z4 = acc[3][mi][ni][e * 2 + p] + bb4;
                    float o1 = sigm_f(z1);
                    float o2 = sigm_f(z2);
                    float o3 = tanh_f(z3);
                    float o4 = sigm_f(z4);
                    float cvj = p ? cv.y : cv.x;
                    oc[p] = cvj * o1 + o2 * o3;
                    oh[p] = tanh_f(cvj) * o4;
                }
                *reinterpret_cast<float2*>(hrow + col) = make_float2(oh[0], oh[1]);
                *reinterpret_cast<float2*>(wrow + col) = make_float2(oc[0], oc[1]);
            }
        }
    }
}

// ---------------- launcher ----------------
extern "C" void kernel_launch(void* const* d_in, const int* in_sizes, int n_in,
                              void* d_out, int out_size) {
    const float* i_ = (const float*)d_in[0];
    const float* h_ = (const float*)d_in[1];
    const float* c_ = (const float*)d_in[2];
    const float* W1 = (const float*)d_in[3];
    const float* b1 = (const float*)d_in[4];
    const float* W2 = (const float*)d_in[5];
    const float* b2 = (const float*)d_in[6];
    const float* W3 = (const float*)d_in[7];
    const float* b3 = (const float*)d_in[8];
    const float* W4 = (const float*)d_in[9];
    const float* b4 = (const float*)d_in[10];
    float* out = (float*)d_out;

    cudaFuncSetAttribute(lstm_gemm_kernel,
                         cudaFuncAttributeMaxDynamicSharedMemorySize, SMEM_TOTAL);

    convert_kernel<<<8192, 256>>>(i_, h_, W1, W2, W3, W4);
    lstm_gemm_kernel<<<GRID, NTHREADS, SMEM_TOTAL>>>(
        c_, b1, b2, b3, b4, out, out + (size_t)BATCH * NDIM);
}